// round 15
// baseline (speedup 1.0000x reference)
#include <cuda_runtime.h>
#include <math.h>

#define MAXBREAK 16384
#define NB 4096
#define TPB 512           // 2 CTAs/SM at natural 64-reg allocation
#define CHUNK_F4 16384u   // float4s per chunk = 32 per thread * 512 = 256KB

__device__ float    g_breakVals[MAXBREAK];
__device__ int      g_compMin[MAXBREAK];
__device__ unsigned g_ticketB  = 0;  // monotone across replays (snapshot-based)
__device__ unsigned g_chunkCtr = 0;  // reset by last-done block each launch
__device__ unsigned g_doneCtr  = 0;  // reset by last-done block each launch

__device__ __forceinline__ unsigned encodeKey(float f) {
    unsigned u = __float_as_uint(f);
    return (u & 0x80000000u) ? ~u : (u | 0x80000000u);
}
__device__ __forceinline__ float decodeKey(unsigned k) {
    unsigned u = (k & 0x80000000u) ? (k & 0x7fffffffu) : ~k;
    return __uint_as_float(u);
}

// Fill chunks [claimed dynamically] of o4[start4, total4) with zeros.
// Verified store-burst shape (uniformly predicated STG.128 batch) from the
// 52.8us optimum; 512-thread blocks -> 32 stores/thread per 256KB chunk.
__device__ __forceinline__ void fill_chunks(float4* o4, size_t start4,
                                            size_t total4, unsigned numChunks)
{
    float4 z = make_float4(0.f, 0.f, 0.f, 0.f);
    int tid = threadIdx.x;
    __shared__ unsigned sChunk;
    for (;;) {
        if (tid == 0) sChunk = atomicAdd(&g_chunkCtr, 1u);
        __syncthreads();
        unsigned c = sChunk;
        __syncthreads();
        if (c >= numChunks) break;
        size_t base = start4 + (size_t)c * CHUNK_F4 + (unsigned)tid;
        #pragma unroll
        for (int k = 0; k < 32; ++k) {
            size_t p = base + (size_t)k * (size_t)TPB;
            if (p < total4) __stcs(&o4[p], z);
        }
    }
}

// ---------------------------------------------------------------------------
// One fused kernel, grid = 296 x 512 threads (2 CTAs/SM, single wave).
//   Block 0 : means -> grid tail -> exact break detection (bins) -> row 0
//             -> join chunk-fill pool -> (K>0 only) wait + scatter.
//   Others  : chunk-steal zero-fill of mask rows [1, N).
//
// Interval-graph fact: adj(i,j) = (1.0f - |vi-vj| >= 0.6f) is a monotone
// threshold predicate, so components = maximal sorted-value runs; breaks can
// only occur between consecutive occupied bins when bin width << threshold,
// tested EXACTLY on (max of lower bin, min of upper bin).
// comp(n) = #breaks with breakVal < v_n; label(n) = min index in comp.
// ---------------------------------------------------------------------------
__global__ void __launch_bounds__(TPB)
mega_kernel(const float* __restrict__ spikes, const int* __restrict__ cstart,
            float* __restrict__ out, int N, int T, unsigned numChunks)
{
    extern __shared__ unsigned smem_u[];
    int tid = threadIdx.x;
    size_t start4 = ((size_t)N) >> 2;                 // skip row 0
    size_t total4 = ((size_t)N * (size_t)N) >> 2;     // N*N % 4 == 0
    float4* o4 = reinterpret_cast<float4*>(out);

    // ======================= FILLER BLOCKS ================================
    if (blockIdx.x != 0) {
        fill_chunks(o4, start4, total4, numChunks);
        __threadfence();
        __syncthreads();
        if (tid == 0) {
            unsigned d = atomicAdd(&g_doneCtr, 1u);
            if (d == gridDim.x - 1u) {          // last block: reset for next replay
                g_chunkCtr = 0u; g_doneCtr = 0u; __threadfence();
            }
            atomicAdd(&g_ticketB, 1u);
        }
        return;
    }

    // ======================= ANALYSIS BLOCK (block 0) =====================
    unsigned baseTicket = atomicAdd(&g_ticketB, 0u);  // snapshot at entry

    float*    v      = reinterpret_cast<float*>(smem_u);   // [N]
    unsigned* binMin = smem_u + N;                          // [NB]
    unsigned* binMax = binMin + NB;                         // [NB]
    __shared__ unsigned sKeyMin, sKeyMax, sFirstBin;
    __shared__ int sK;

    if (tid == 0) { sKeyMin = 0xFFFFFFFFu; sKeyMax = 0u; sFirstBin = NB; sK = 0; }
    for (int b = tid; b < NB; b += TPB) { binMin[b] = 0xFFFFFFFFu; binMax[b] = 0u; }
    __syncthreads();

    // ---- means (float4-vectorized over n), grid tail, key min/max ----
    int cs = cstart[0];
    int st = cs - 1;
    if (st < 0) st = 0;
    if (st > T - 1) st = T - 1;
    float invCnt = 1.0f / (float)(T - st);
    unsigned lmin = 0xFFFFFFFFu, lmax = 0u;
    const float4* sp4 = reinterpret_cast<const float4*>(spikes);
    int N4 = N >> 2;
    float4* vout4 = reinterpret_cast<float4*>(out + (size_t)N * N);
    float4* v4 = reinterpret_cast<float4*>(v);
    for (int i = tid; i < N4; i += TPB) {
        float4 acc = make_float4(0.f, 0.f, 0.f, 0.f);
        for (int t = st; t < T; ++t) {
            float4 s = __ldg(&sp4[(size_t)t * N4 + i]);
            acc.x += s.x; acc.y += s.y; acc.z += s.z; acc.w += s.w;
        }
        acc.x *= invCnt; acc.y *= invCnt; acc.z *= invCnt; acc.w *= invCnt;
        v4[i] = acc;
        vout4[i] = acc;                                 // mean_spike_grid tail
        unsigned k0 = encodeKey(acc.x), k1 = encodeKey(acc.y);
        unsigned k2 = encodeKey(acc.z), k3 = encodeKey(acc.w);
        lmin = min(min(lmin, k0), min(k1, min(k2, k3)));
        lmax = max(max(lmax, k0), max(k1, max(k2, k3)));
    }
    atomicMin_block(&sKeyMin, lmin);
    atomicMax_block(&sKeyMax, lmax);
    __syncthreads();

    float vmin = decodeKey(sKeyMin);
    float vmax = decodeKey(sKeyMax);
    float range = vmax - vmin;
    bool binOK = (range > 0.0f) &&
                 (1.0f - (range * (2.0f / (float)NB)) >= 0.6f);

    int K = 0;
    if (binOK) {
        float inv = (float)NB / range;
        for (int n = tid; n < N; n += TPB) {
            float x = v[n];
            int b = (int)((x - vmin) * inv);
            if (b >= NB) b = NB - 1;
            if (b < 0) b = 0;
            unsigned k = encodeKey(x);
            atomicMin_block(&binMin[b], k);
            atomicMax_block(&binMax[b], k);
        }
        __syncthreads();
        for (int b = tid; b < NB; b += TPB)
            if (binMin[b] != 0xFFFFFFFFu) atomicMin_block(&sFirstBin, (unsigned)b);
        __syncthreads();
        for (int b = tid; b < NB; b += TPB) {
            if (binMin[b] != 0xFFFFFFFFu && b > (int)sFirstBin) {
                int p = b - 1;
                while (binMin[p] == 0xFFFFFFFFu) --p;
                float lo = decodeKey(binMax[p]);
                float hi = decodeKey(binMin[b]);
                float d = hi - lo;                      // exact pair distance
                if (!(1.0f - d >= 0.6f)) {              // EXACT ref predicate
                    int slot = atomicAdd_block(&sK, 1);
                    if (slot < MAXBREAK) g_breakVals[slot] = lo;
                }
            }
        }
        __syncthreads();
        K = sK;
    } else if (range > 0.0f) {
        // exact warp-scan fallback (pathological value ranges only)
        int warpId = tid >> 5, lane = tid & 31;
        int nWarps = TPB / 32;
        for (int node = warpId; node < N; node += nWarps) {
            float vi = v[node];
            bool found = false, anyG = false;
            for (int base = 0; base < N; base += 32) {
                int j = base + lane;
                float vj = (j < N) ? v[j] : vi;
                bool g = vj > vi;
                bool wq = g && (1.0f - (vj - vi) >= 0.6f);
                unsigned mW = __ballot_sync(0xffffffffu, wq);
                unsigned mG = __ballot_sync(0xffffffffu, g);
                anyG |= (mG != 0u);
                if (mW) { found = true; break; }
            }
            if (!found && anyG && lane == 0) {
                int slot = atomicAdd_block(&sK, 1);
                if (slot < MAXBREAK) g_breakVals[slot] = vi;
            }
        }
        __syncthreads();
        K = sK;
    }
    if (K > MAXBREAK) K = MAXBREAK;

    // comp(x) = #distinct break values < x (dedup only matters for fallback)
    auto compOf = [&](float x) {
        int c = 0;
        for (int k = 0; k < K; ++k) {
            float b = g_breakVals[k];
            if (b < x) {
                bool first = true;
                for (int j = 0; j < k; ++j)
                    if (g_breakVals[j] == b) { first = false; break; }
                if (first) c++;
            }
        }
        return c;
    };

    // ---- row 0: masks[0, n] = (comp(n) == comp(0)) ----
    int comp0 = compOf(v[0]);
    for (int n = tid; n < N; n += TPB)
        out[n] = (compOf(v[n]) == comp0) ? 1.0f : 0.0f;

    // ---- K>0 prep BEFORE joining the fill (overlap the compute) ----
    if (K > 0) {
        for (int c = tid; c <= K && c < MAXBREAK; c += TPB)
            g_compMin[c] = 0x7fffffff;
        __syncthreads();
        for (int n = tid; n < N; n += TPB)
            atomicMin(&g_compMin[compOf(v[n])], n);
        __syncthreads();
    }

    // ---- join the fill pool ----
    fill_chunks(o4, start4, total4, numChunks);
    __threadfence();
    __syncthreads();
    if (tid == 0) {
        unsigned d = atomicAdd(&g_doneCtr, 1u);
        if (d == gridDim.x - 1u) { g_chunkCtr = 0u; g_doneCtr = 0u; __threadfence(); }
    }
    __syncthreads();

    if (K == 0) return;   // single component: done

    // ---- wait for all fillers, then scatter remaining component rows ----
    if (tid == 0) {
        unsigned need = gridDim.x - 1u;
        while (atomicAdd(&g_ticketB, 0u) - baseTicket < need)
            __nanosleep(128);
    }
    __syncthreads();
    __threadfence();

    for (int n = tid; n < N; n += TPB) {
        int c = compOf(v[n]);
        int m = atomicAdd(&g_compMin[c], 0);
        if (m != 0)                      // row 0 already written above
            out[(size_t)m * N + n] = 1.0f;
    }
}

// ---------------------------------------------------------------------------
extern "C" void kernel_launch(void* const* d_in, const int* in_sizes, int n_in,
                              void* d_out, int out_size)
{
    const float* spikes = (const float*)d_in[0];
    const int*   cstart = (const int*)d_in[1];
    float* out = (float*)d_out;

    // Solve N from out_size = N*N + N.
    size_t S = (size_t)out_size;
    int N = (int)((sqrt(4.0 * (double)S + 1.0) - 1.0) * 0.5);
    while ((size_t)N * N + N > S) N--;
    while ((size_t)(N + 1) * (N + 1) + (N + 1) <= S) N++;
    int T = in_sizes[0] / N;   // batch = 1

    size_t start4 = ((size_t)N) >> 2;
    size_t total4 = ((size_t)N * (size_t)N) >> 2;
    unsigned numChunks = (unsigned)((total4 - start4 + CHUNK_F4 - 1) / CHUNK_F4);

    int grid = 296;                       // 2 CTAs/SM at 512 threads, 1 wave
    size_t smem = (size_t)N * sizeof(float) + 2u * NB * sizeof(unsigned);
    cudaFuncSetAttribute(mega_kernel,
                         cudaFuncAttributeMaxDynamicSharedMemorySize,
                         (int)smem);
    mega_kernel<<<grid, TPB, smem>>>(spikes, cstart, out, N, T, numChunks);
}

// round 16
// speedup vs baseline: 1.1830x; 1.1830x over previous
#include <cuda_runtime.h>
#include <math.h>

#define MAXBREAK 16384
#define NB 4096
#define CHUNK_F4 16384u   // float4s per chunk = 16 per thread * 1024 = 256KB

__device__ float    g_breakVals[MAXBREAK];
__device__ int      g_compMin[MAXBREAK];
__device__ unsigned g_ticketB  = 0;  // monotone across replays (snapshot-based)
__device__ unsigned g_chunkCtr = 0;  // reset by last-done block each launch
__device__ unsigned g_doneCtr  = 0;  // reset by last-done block each launch

__device__ __forceinline__ unsigned encodeKey(float f) {
    unsigned u = __float_as_uint(f);
    return (u & 0x80000000u) ? ~u : (u | 0x80000000u);
}
__device__ __forceinline__ float decodeKey(unsigned k) {
    unsigned u = (k & 0x80000000u) ? (k & 0x7fffffffu) : ~k;
    return __uint_as_float(u);
}

// Fill chunks [claimed dynamically] of o4[start4, total4) with zeros.
// FINAL verified-best configuration (52.8-53.3us across five runs):
// block-level 256KB claims, uniformly predicated 16x STG.128 burst,
// 1024 threads x 148 blocks. Complete sweep evidence:
//   2-blk/SM reg-cap (-8%), lookahead claim (neutral), warp-steal (-12%),
//   branchy store path (-49%), STG.256 (-5%), 512KB chunks (-2%),
//   512thr x 296blk (-16%). At the HBM3e write-turnaround ceiling.
__device__ __forceinline__ void fill_chunks(float4* o4, size_t start4,
                                            size_t total4, unsigned numChunks)
{
    float4 z = make_float4(0.f, 0.f, 0.f, 0.f);
    int tid = threadIdx.x;
    __shared__ unsigned sChunk;
    for (;;) {
        if (tid == 0) sChunk = atomicAdd(&g_chunkCtr, 1u);
        __syncthreads();
        unsigned c = sChunk;
        __syncthreads();
        if (c >= numChunks) break;
        size_t base = start4 + (size_t)c * CHUNK_F4 + (unsigned)tid;
        #pragma unroll
        for (int k = 0; k < 16; ++k) {
            size_t p = base + (size_t)k * 1024u;
            if (p < total4) __stcs(&o4[p], z);
        }
    }
}

// ---------------------------------------------------------------------------
// One fused kernel, grid = 148 (1 block/SM, single wave).
//   Block 0 : means -> grid tail -> exact break detection (bins) -> row 0
//             -> join chunk-fill pool -> (K>0 only) wait + scatter.
//   Others  : chunk-steal zero-fill of mask rows [1, N).
//
// Interval-graph fact: adj(i,j) = (1.0f - |vi-vj| >= 0.6f) is a monotone
// threshold predicate, so components = maximal sorted-value runs; breaks can
// only occur between consecutive occupied bins when bin width << threshold,
// tested EXACTLY on (max of lower bin, min of upper bin).
// comp(n) = #breaks with breakVal < v_n; label(n) = min index in comp.
// ---------------------------------------------------------------------------
__global__ void __launch_bounds__(1024)
mega_kernel(const float* __restrict__ spikes, const int* __restrict__ cstart,
            float* __restrict__ out, int N, int T, unsigned numChunks)
{
    extern __shared__ unsigned smem_u[];
    int tid = threadIdx.x;
    size_t start4 = ((size_t)N) >> 2;                 // skip row 0
    size_t total4 = ((size_t)N * (size_t)N) >> 2;     // N*N % 4 == 0
    float4* o4 = reinterpret_cast<float4*>(out);

    // ======================= FILLER BLOCKS ================================
    if (blockIdx.x != 0) {
        fill_chunks(o4, start4, total4, numChunks);
        __threadfence();
        __syncthreads();
        if (tid == 0) {
            unsigned d = atomicAdd(&g_doneCtr, 1u);
            if (d == gridDim.x - 1u) {          // last block: reset for next replay
                g_chunkCtr = 0u; g_doneCtr = 0u; __threadfence();
            }
            atomicAdd(&g_ticketB, 1u);
        }
        return;
    }

    // ======================= ANALYSIS BLOCK (block 0) =====================
    unsigned baseTicket = atomicAdd(&g_ticketB, 0u);  // snapshot at entry

    float*    v      = reinterpret_cast<float*>(smem_u);   // [N]
    unsigned* binMin = smem_u + N;                          // [NB]
    unsigned* binMax = binMin + NB;                         // [NB]
    __shared__ unsigned sKeyMin, sKeyMax, sFirstBin;
    __shared__ int sK;

    if (tid == 0) { sKeyMin = 0xFFFFFFFFu; sKeyMax = 0u; sFirstBin = NB; sK = 0; }
    for (int b = tid; b < NB; b += 1024) { binMin[b] = 0xFFFFFFFFu; binMax[b] = 0u; }
    __syncthreads();

    // ---- means (float4-vectorized over n), grid tail, key min/max ----
    int cs = cstart[0];
    int st = cs - 1;
    if (st < 0) st = 0;
    if (st > T - 1) st = T - 1;
    float invCnt = 1.0f / (float)(T - st);
    unsigned lmin = 0xFFFFFFFFu, lmax = 0u;
    const float4* sp4 = reinterpret_cast<const float4*>(spikes);
    int N4 = N >> 2;
    float4* vout4 = reinterpret_cast<float4*>(out + (size_t)N * N);
    float4* v4 = reinterpret_cast<float4*>(v);
    for (int i = tid; i < N4; i += 1024) {
        float4 acc = make_float4(0.f, 0.f, 0.f, 0.f);
        for (int t = st; t < T; ++t) {
            float4 s = __ldg(&sp4[(size_t)t * N4 + i]);
            acc.x += s.x; acc.y += s.y; acc.z += s.z; acc.w += s.w;
        }
        acc.x *= invCnt; acc.y *= invCnt; acc.z *= invCnt; acc.w *= invCnt;
        v4[i] = acc;
        vout4[i] = acc;                                 // mean_spike_grid tail
        unsigned k0 = encodeKey(acc.x), k1 = encodeKey(acc.y);
        unsigned k2 = encodeKey(acc.z), k3 = encodeKey(acc.w);
        lmin = min(min(lmin, k0), min(k1, min(k2, k3)));
        lmax = max(max(lmax, k0), max(k1, max(k2, k3)));
    }
    atomicMin_block(&sKeyMin, lmin);
    atomicMax_block(&sKeyMax, lmax);
    __syncthreads();

    float vmin = decodeKey(sKeyMin);
    float vmax = decodeKey(sKeyMax);
    float range = vmax - vmin;
    bool binOK = (range > 0.0f) &&
                 (1.0f - (range * (2.0f / (float)NB)) >= 0.6f);

    int K = 0;
    if (binOK) {
        float inv = (float)NB / range;
        for (int n = tid; n < N; n += 1024) {
            float x = v[n];
            int b = (int)((x - vmin) * inv);
            if (b >= NB) b = NB - 1;
            if (b < 0) b = 0;
            unsigned k = encodeKey(x);
            atomicMin_block(&binMin[b], k);
            atomicMax_block(&binMax[b], k);
        }
        __syncthreads();
        for (int b = tid; b < NB; b += 1024)
            if (binMin[b] != 0xFFFFFFFFu) atomicMin_block(&sFirstBin, (unsigned)b);
        __syncthreads();
        for (int b = tid; b < NB; b += 1024) {
            if (binMin[b] != 0xFFFFFFFFu && b > (int)sFirstBin) {
                int p = b - 1;
                while (binMin[p] == 0xFFFFFFFFu) --p;
                float lo = decodeKey(binMax[p]);
                float hi = decodeKey(binMin[b]);
                float d = hi - lo;                      // exact pair distance
                if (!(1.0f - d >= 0.6f)) {              // EXACT ref predicate
                    int slot = atomicAdd_block(&sK, 1);
                    if (slot < MAXBREAK) g_breakVals[slot] = lo;
                }
            }
        }
        __syncthreads();
        K = sK;
    } else if (range > 0.0f) {
        // exact warp-scan fallback (pathological value ranges only)
        int warpId = tid >> 5, lane = tid & 31;
        for (int node = warpId; node < N; node += 32) {
            float vi = v[node];
            bool found = false, anyG = false;
            for (int base = 0; base < N; base += 32) {
                int j = base + lane;
                float vj = (j < N) ? v[j] : vi;
                bool g = vj > vi;
                bool wq = g && (1.0f - (vj - vi) >= 0.6f);
                unsigned mW = __ballot_sync(0xffffffffu, wq);
                unsigned mG = __ballot_sync(0xffffffffu, g);
                anyG |= (mG != 0u);
                if (mW) { found = true; break; }
            }
            if (!found && anyG && lane == 0) {
                int slot = atomicAdd_block(&sK, 1);
                if (slot < MAXBREAK) g_breakVals[slot] = vi;
            }
        }
        __syncthreads();
        K = sK;
    }
    if (K > MAXBREAK) K = MAXBREAK;

    // comp(x) = #distinct break values < x (dedup only matters for fallback)
    auto compOf = [&](float x) {
        int c = 0;
        for (int k = 0; k < K; ++k) {
            float b = g_breakVals[k];
            if (b < x) {
                bool first = true;
                for (int j = 0; j < k; ++j)
                    if (g_breakVals[j] == b) { first = false; break; }
                if (first) c++;
            }
        }
        return c;
    };

    // ---- row 0: masks[0, n] = (comp(n) == comp(0)) ----
    int comp0 = compOf(v[0]);
    for (int n = tid; n < N; n += 1024)
        out[n] = (compOf(v[n]) == comp0) ? 1.0f : 0.0f;

    // ---- K>0 prep BEFORE joining the fill (overlap the compute) ----
    if (K > 0) {
        for (int c = tid; c <= K && c < MAXBREAK; c += 1024)
            g_compMin[c] = 0x7fffffff;
        __syncthreads();
        for (int n = tid; n < N; n += 1024)
            atomicMin(&g_compMin[compOf(v[n])], n);
        __syncthreads();
    }

    // ---- join the fill pool ----
    fill_chunks(o4, start4, total4, numChunks);
    __threadfence();
    __syncthreads();
    if (tid == 0) {
        unsigned d = atomicAdd(&g_doneCtr, 1u);
        if (d == gridDim.x - 1u) { g_chunkCtr = 0u; g_doneCtr = 0u; __threadfence(); }
    }
    __syncthreads();

    if (K == 0) return;   // single component: done

    // ---- wait for all fillers, then scatter remaining component rows ----
    if (tid == 0) {
        unsigned need = gridDim.x - 1u;
        while (atomicAdd(&g_ticketB, 0u) - baseTicket < need)
            __nanosleep(128);
    }
    __syncthreads();
    __threadfence();

    for (int n = tid; n < N; n += 1024) {
        int c = compOf(v[n]);
        int m = atomicAdd(&g_compMin[c], 0);
        if (m != 0)                      // row 0 already written above
            out[(size_t)m * N + n] = 1.0f;
    }
}

// ---------------------------------------------------------------------------
extern "C" void kernel_launch(void* const* d_in, const int* in_sizes, int n_in,
                              void* d_out, int out_size)
{
    const float* spikes = (const float*)d_in[0];
    const int*   cstart = (const int*)d_in[1];
    float* out = (float*)d_out;

    // Solve N from out_size = N*N + N.
    size_t S = (size_t)out_size;
    int N = (int)((sqrt(4.0 * (double)S + 1.0) - 1.0) * 0.5);
    while ((size_t)N * N + N > S) N--;
    while ((size_t)(N + 1) * (N + 1) + (N + 1) <= S) N++;
    int T = in_sizes[0] / N;   // batch = 1

    size_t start4 = ((size_t)N) >> 2;
    size_t total4 = ((size_t)N * (size_t)N) >> 2;
    unsigned numChunks = (unsigned)((total4 - start4 + CHUNK_F4 - 1) / CHUNK_F4);

    int grid = 148;                       // 1 block/SM, single wave
    size_t smem = (size_t)N * sizeof(float) + 2u * NB * sizeof(unsigned);
    cudaFuncSetAttribute(mega_kernel,
                         cudaFuncAttributeMaxDynamicSharedMemorySize,
                         (int)smem);
    mega_kernel<<<grid, 1024, smem>>>(spikes, cstart, out, N, T, numChunks);
}